// round 1
// baseline (speedup 1.0000x reference)
#include <cuda_runtime.h>
#include <math.h>

#define BB 4
#define NN 5
#define KK 5
#define QQ 5
#define LL 128
#define FF 768
#define NQv (NN*QQ)          // 25
#define EPSF 1e-8f
#define PRED_ELEMS (BB*NQv*LL)   // 12800

// Scratch (no cudaMalloc allowed)
__device__ __align__(16) float g_proto[BB*NN*4*FF];      // class prototypes per (b,n)
__device__ __align__(16) float g_sentproto[BB*NN*FF];    // sentence prototypes
__device__ int   g_sentpred[BB*NQv];
__device__ float g_scratch[PRED_ELEMS + 4];              // fallback sink

// ---------------------------------------------------------------------------
// Kernel A: per-(b,n) class prototypes (tags 1..4) and sentence prototypes.
// grid = (B*N, F/128), block = 512 threads: tid%128 -> f lane, tid/128 -> row group.
// ---------------------------------------------------------------------------
__global__ void proto_kernel(const float* __restrict__ sup,
                             const int*   __restrict__ sem,
                             const int*   __restrict__ sam) {
    const int bn    = blockIdx.x;            // b*N + n
    const int fbase = blockIdx.y * 128;
    const int tid   = threadIdx.x;
    const int fl    = tid & 127;             // f lane
    const int grp   = tid >> 7;              // 0..3 row group
    const int f     = fbase + fl;

    __shared__ signed char s_cls[KK*LL];
    __shared__ int   s_den[4];
    __shared__ float s_part[4][4][128];      // [group][class][f]

    if (tid < 4) s_den[tid] = 0;
    __syncthreads();

    const int mbase = bn * KK * LL;
    for (int i = tid; i < KK*LL; i += 512) {
        int lab = sem[mbase + i];
        int att = sam[mbase + i];
        int c = (lab >= 1 && lab <= 4 && att > 0) ? (lab - 1) : -1;
        s_cls[i] = (signed char)c;
        if (c >= 0) atomicAdd(&s_den[c], 1);
    }
    __syncthreads();

    const float* p = sup + (size_t)bn * (KK*LL*FF) + f;
    float a0 = 0.f, a1 = 0.f, a2 = 0.f, a3 = 0.f;
    #pragma unroll 4
    for (int i = grp; i < KK*LL; i += 4) {
        int c = s_cls[i];
        if (c < 0) continue;
        float v = p[(size_t)i * FF];
        if      (c == 0) a0 += v;
        else if (c == 1) a1 += v;
        else if (c == 2) a2 += v;
        else             a3 += v;
    }
    s_part[grp][0][fl] = a0;
    s_part[grp][1][fl] = a1;
    s_part[grp][2][fl] = a2;
    s_part[grp][3][fl] = a3;
    __syncthreads();

    if (tid < 128) {
        int ff = tid;
        int obase = (bn * 4) * FF + fbase + ff;
        #pragma unroll
        for (int c = 0; c < 4; c++) {
            float s = s_part[0][c][ff] + s_part[1][c][ff] +
                      s_part[2][c][ff] + s_part[3][c][ff];
            g_proto[obase + c*FF] = s / ((float)s_den[c] + EPSF);
        }
        // sentence prototype: mean over k of support_emb[b,n,k,0,:]
        float sp = 0.f;
        const float* ps = sup + (size_t)bn * (KK*LL*FF) + fbase + ff;
        #pragma unroll
        for (int k = 0; k < KK; k++) sp += ps[(size_t)k * LL * FF];
        g_sentproto[bn*FF + fbase + ff] = sp * (1.0f / (float)KK);
    }
}

// ---------------------------------------------------------------------------
// Kernel B: sentence logits, log-softmax loss, sentence argmax prediction.
// grid = B*NQ blocks, 256 threads.
// ---------------------------------------------------------------------------
__global__ void sent_kernel(const float* __restrict__ qemb,
                            const int*   __restrict__ slab,
                            float* loss_ptr) {
    const int bq  = blockIdx.x;
    const int b   = bq / NQv;
    const int tid = threadIdx.x;
    const int wid = tid >> 5, lane = tid & 31;

    const float* qrow = qemb + (size_t)bq * LL * FF;  // l = 0 row
    float d2[NN];
    #pragma unroll
    for (int n = 0; n < NN; n++) d2[n] = 0.f;

    for (int f = tid; f < FF; f += 256) {
        float qv = qrow[f];
        #pragma unroll
        for (int n = 0; n < NN; n++) {
            float d = g_sentproto[(b*NN + n)*FF + f] - qv;
            d2[n] += d * d;
        }
    }
    #pragma unroll
    for (int off = 16; off > 0; off >>= 1) {
        #pragma unroll
        for (int n = 0; n < NN; n++)
            d2[n] += __shfl_xor_sync(0xffffffffu, d2[n], off);
    }
    __shared__ float s_red[8][NN];
    if (lane == 0) {
        #pragma unroll
        for (int n = 0; n < NN; n++) s_red[wid][n] = d2[n];
    }
    __syncthreads();
    if (tid == 0) {
        float lg[NN];
        #pragma unroll
        for (int n = 0; n < NN; n++) {
            float s = 0.f;
            #pragma unroll
            for (int w = 0; w < 8; w++) s += s_red[w][n];
            lg[n] = -s;
        }
        float mx = lg[0]; int am = 0;
        #pragma unroll
        for (int n = 1; n < NN; n++) if (lg[n] > mx) { mx = lg[n]; am = n; }
        float se = 0.f;
        #pragma unroll
        for (int n = 0; n < NN; n++) se += expf(lg[n] - mx);
        int lab = slab[bq];
        float logp = lg[lab] - mx - logf(se);
        atomicAdd(loss_ptr, -logp / (float)(BB*NQv));
        g_sentpred[bq] = am;
    }
}

// ---------------------------------------------------------------------------
// Kernel C: token logits, BCE token loss, per-class argmax, final prediction.
// grid = B*NQ blocks, 256 threads (8 warps, each warp handles strided l rows).
// ---------------------------------------------------------------------------
__global__ void token_kernel(const float* __restrict__ qemb,
                             const int*   __restrict__ qem,
                             const int*   __restrict__ qatt,
                             const int*   __restrict__ slab,
                             float* loss_ptr,
                             float* pred_out) {
    const int bq   = blockIdx.x;
    const int b    = bq / NQv;
    const int tid  = threadIdx.x;
    const int wid  = tid >> 5, lane = tid & 31;
    const int FV   = FF / 4;   // 192 float4 per row

    __shared__ float4 s_proto[4 * (FF/4)];
    __shared__ float  s_p2[4];
    __shared__ float  s_ml[LL * 4];
    __shared__ float  s_wb[8], s_wa[8];
    __shared__ int    s_idx[4];

    const int cond = slab[bq];
    const float4* gp = (const float4*)(g_proto + (size_t)((b*NN + cond) * 4) * FF);
    for (int i = tid; i < 4 * FV; i += 256) s_proto[i] = gp[i];
    __syncthreads();

    if (wid < 4) {  // warp c computes p2[c]
        float s = 0.f;
        #pragma unroll
        for (int j = 0; j < FV/32; j++) {
            float4 v = s_proto[wid*FV + lane + 32*j];
            s += v.x*v.x + v.y*v.y + v.z*v.z + v.w*v.w;
        }
        #pragma unroll
        for (int off = 16; off > 0; off >>= 1) s += __shfl_xor_sync(0xffffffffu, s, off);
        if (lane == 0) s_p2[wid] = s;
    }
    __syncthreads();

    const float4* qbase = (const float4*)(qemb + (size_t)bq * LL * FF);
    const int mlbase = bq * LL;
    float bce_acc = 0.f, att_acc = 0.f;

    for (int l = wid; l < LL; l += 8) {
        const float4* qr = qbase + l * FV;
        float q2 = 0.f, c0 = 0.f, c1 = 0.f, c2 = 0.f, c3 = 0.f;
        #pragma unroll
        for (int j = 0; j < FV/32; j++) {
            int o = lane + 32*j;
            float4 v  = qr[o];
            float4 w0 = s_proto[0*FV + o];
            float4 w1 = s_proto[1*FV + o];
            float4 w2 = s_proto[2*FV + o];
            float4 w3 = s_proto[3*FV + o];
            q2 += v.x*v.x + v.y*v.y + v.z*v.z + v.w*v.w;
            c0 += v.x*w0.x + v.y*w0.y + v.z*w0.z + v.w*w0.w;
            c1 += v.x*w1.x + v.y*w1.y + v.z*w1.z + v.w*w1.w;
            c2 += v.x*w2.x + v.y*w2.y + v.z*w2.z + v.w*w2.w;
            c3 += v.x*w3.x + v.y*w3.y + v.z*w3.z + v.w*w3.w;
        }
        #pragma unroll
        for (int off = 16; off > 0; off >>= 1) {
            q2 += __shfl_xor_sync(0xffffffffu, q2, off);
            c0 += __shfl_xor_sync(0xffffffffu, c0, off);
            c1 += __shfl_xor_sync(0xffffffffu, c1, off);
            c2 += __shfl_xor_sync(0xffffffffu, c2, off);
            c3 += __shfl_xor_sync(0xffffffffu, c3, off);
        }
        float att = (float)qatt[mlbase + l];
        int   em  = qem[mlbase + l];
        float tl[4];
        tl[0] = -(q2 + s_p2[0] - 2.f*c0);
        tl[1] = -(q2 + s_p2[1] - 2.f*c1);
        tl[2] = -(q2 + s_p2[2] - 2.f*c2);
        tl[3] = -(q2 + s_p2[3] - 2.f*c3);
        float bl = 0.f;
        #pragma unroll
        for (int c = 0; c < 4; c++) {
            float x = tl[c];
            float t = (em == c + 1) ? 1.f : 0.f;
            bl += fmaxf(x, 0.f) - x * t + log1pf(expf(-fabsf(x)));
        }
        bce_acc += bl * att;
        att_acc += att;
        if (lane < 4) s_ml[l*4 + lane] = tl[lane] - 1000.f * (1.f - att);
    }

    if (lane == 0) { s_wb[wid] = bce_acc; s_wa[wid] = att_acc; }
    __syncthreads();

    if (tid == 0) {
        float bs = 0.f, as = 0.f;
        #pragma unroll
        for (int w = 0; w < 8; w++) { bs += s_wb[w]; as += s_wa[w]; }
        float per = bs / (as * 4.f + EPSF);
        atomicAdd(loss_ptr, per / (float)(BB*NQv));
    }
    if (tid < 4) {  // first-occurrence argmax over l for class tid
        float best = s_ml[0*4 + tid]; int bi = 0;
        for (int l = 1; l < LL; l++) {
            float v = s_ml[l*4 + tid];
            if (v > best) { best = v; bi = l; }
        }
        s_idx[tid] = bi;
    }
    __syncthreads();

    if (tid < LL) {
        int pos = tid;
        int i0 = s_idx[0], i1 = s_idx[1], i2 = s_idx[2], i3 = s_idx[3];
        int pred = 0;
        if (pos == i0)                pred = 1;
        if (pos > i0 && pos <= i1)    pred = 2;
        if (pos == i2)                pred = 3;
        if (pos > i2 && pos <= i3)    pred = 4;
        int sp = g_sentpred[bq];
        int fp = (pred != 0) ? (4*sp + pred) : 0;
        pred_out[mlbase + tid] = (float)fp;
    }
}

__global__ void init_kernel(float* loss) {
    if (threadIdx.x == 0) *loss = 0.f;
}

// ---------------------------------------------------------------------------
extern "C" void kernel_launch(void* const* d_in, const int* in_sizes, int n_in,
                              void* d_out, int out_size) {
    const float* sup  = (const float*)d_in[0];
    const float* qemb = (const float*)d_in[1];
    const int*   sem  = (const int*)d_in[2];
    const int*   qem  = (const int*)d_in[3];
    const int*   sam  = (const int*)d_in[4];
    const int*   qatt = (const int*)d_in[5];
    const int*   slab = (const int*)d_in[6];

    float* out = (float*)d_out;
    float* scratch = nullptr;
    cudaGetSymbolAddress((void**)&scratch, g_scratch);

    float* loss_ptr;
    float* pred_ptr;
    if (out_size >= PRED_ELEMS + 1) {        // [loss, final_pred...] (expected)
        loss_ptr = out;
        pred_ptr = out + 1;
    } else if (out_size == PRED_ELEMS) {     // pred only
        loss_ptr = scratch + PRED_ELEMS;
        pred_ptr = out;
    } else {                                 // loss only
        loss_ptr = out;
        pred_ptr = scratch;
    }

    init_kernel<<<1, 32>>>(loss_ptr);
    proto_kernel<<<dim3(BB*NN, FF/128), 512>>>(sup, sem, sam);
    sent_kernel<<<BB*NQv, 256>>>(qemb, slab, loss_ptr);
    token_kernel<<<BB*NQv, 256>>>(qemb, qem, qatt, slab, loss_ptr, pred_ptr);
}

// round 3
// speedup vs baseline: 1.8320x; 1.8320x over previous
#include <cuda_runtime.h>
#include <math.h>

#define BB 4
#define NN 5
#define KK 5
#define QQ 5
#define LL 128
#define FF 768
#define NQv (NN*QQ)              // 25
#define BQ  (BB*NQv)             // 100
#define EPSF 1e-8f
#define PRED_ELEMS (BB*NQv*LL)   // 12800
#define ZSPLIT 4
#define ROWS_PER_Z (KK*LL/ZSPLIT)   // 160
#define LSEG 8
#define LPB (LL/LSEG)               // 16 l-rows per token block

// Scratch (no cudaMalloc allowed)
__device__ __align__(16) float g_proto[BB*NN*4*FF];             // class prototypes
__device__ __align__(16) float g_partial[ZSPLIT*BB*NN*4*FF];    // z-partial sums
__device__ __align__(16) float g_sentproto[BB*NN*FF];
__device__ int   g_den[BB*NN*4];
__device__ int   g_sentpred[BQ];
__device__ float g_bce[BQ];
__device__ float g_segv[BQ*LSEG*4];
__device__ int   g_segi[BQ*LSEG*4];
__device__ float g_scratch[PRED_ELEMS + 4];

// ---------------------------------------------------------------------------
// init + denominators. Block 0 zeroes loss/bce; blocks 1..20 compute g_den[bn].
// ---------------------------------------------------------------------------
__global__ void init_den_kernel(const int* __restrict__ sem,
                                const int* __restrict__ sam,
                                float* loss_ptr) {
    const int bx  = blockIdx.x;
    const int tid = threadIdx.x;
    if (bx == 0) {
        if (tid == 0) *loss_ptr = 0.f;
        if (tid < BQ) g_bce[tid] = 0.f;
        return;
    }
    const int bn = bx - 1;
    __shared__ int s_den[4];
    if (tid < 4) s_den[tid] = 0;
    __syncthreads();
    const int mbase = bn * KK * LL;
    for (int i = tid; i < KK*LL; i += 256) {
        int lab = sem[mbase + i];
        int att = sam[mbase + i];
        if (lab >= 1 && lab <= 4 && att > 0) atomicAdd(&s_den[lab-1], 1);
    }
    __syncthreads();
    if (tid < 4) g_den[bn*4 + tid] = s_den[tid];
}

// ---------------------------------------------------------------------------
// proto partial sums. grid=(B*N, F/128, ZSPLIT), block=512.
// z-chunk handles rows [z*160, (z+1)*160). grp (tid>>7) strides within chunk.
// ---------------------------------------------------------------------------
__global__ void proto_partial_kernel(const float* __restrict__ sup,
                                     const int*   __restrict__ sem,
                                     const int*   __restrict__ sam) {
    const int bn    = blockIdx.x;
    const int fbase = blockIdx.y * 128;
    const int z     = blockIdx.z;
    const int tid   = threadIdx.x;
    const int fl    = tid & 127;
    const int grp   = tid >> 7;
    const int f     = fbase + fl;
    const int r0    = z * ROWS_PER_Z;

    __shared__ signed char s_cls[ROWS_PER_Z];
    __shared__ float s_part[4][4][128];

    const int mbase = bn * KK * LL + r0;
    for (int i = tid; i < ROWS_PER_Z; i += 512) {
        int lab = sem[mbase + i];
        int att = sam[mbase + i];
        s_cls[i] = (signed char)((lab >= 1 && lab <= 4 && att > 0) ? (lab - 1) : -1);
    }
    __syncthreads();

    const float* p = sup + (size_t)(bn * KK * LL + r0) * FF + f;
    float a0 = 0.f, a1 = 0.f, a2 = 0.f, a3 = 0.f;
    #pragma unroll 4
    for (int i = grp; i < ROWS_PER_Z; i += 4) {
        int c = s_cls[i];
        if (c < 0) continue;
        float v = __ldg(p + (size_t)i * FF);
        if      (c == 0) a0 += v;
        else if (c == 1) a1 += v;
        else if (c == 2) a2 += v;
        else             a3 += v;
    }
    s_part[grp][0][fl] = a0;
    s_part[grp][1][fl] = a1;
    s_part[grp][2][fl] = a2;
    s_part[grp][3][fl] = a3;
    __syncthreads();

    if (tid < 128) {
        int obase = ((z*BB*NN + bn) * 4) * FF + fbase + tid;
        #pragma unroll
        for (int c = 0; c < 4; c++) {
            g_partial[obase + c*FF] =
                s_part[0][c][tid] + s_part[1][c][tid] +
                s_part[2][c][tid] + s_part[3][c][tid];
        }
    }
}

// ---------------------------------------------------------------------------
// normalize partials -> g_proto; also sentence prototypes. grid=(20,6), 128thr.
// ---------------------------------------------------------------------------
__global__ void proto_norm_kernel(const float* __restrict__ sup) {
    const int bn    = blockIdx.x;
    const int fbase = blockIdx.y * 128;
    const int tid   = threadIdx.x;
    const int f     = fbase + tid;

    #pragma unroll
    for (int c = 0; c < 4; c++) {
        int idx = ((bn * 4) + c) * FF + f;
        float s = 0.f;
        #pragma unroll
        for (int z = 0; z < ZSPLIT; z++)
            s += g_partial[(z*BB*NN*4)*FF + idx];
        g_proto[idx] = s / ((float)g_den[bn*4 + c] + EPSF);
    }
    float sp = 0.f;
    const float* ps = sup + (size_t)bn * (KK*LL*FF) + f;
    #pragma unroll
    for (int k = 0; k < KK; k++) sp += __ldg(ps + (size_t)k * LL * FF);
    g_sentproto[bn*FF + f] = sp * (1.0f / (float)KK);
}

// ---------------------------------------------------------------------------
// sentence logits / loss / pred. grid=BQ, 256 threads.
// ---------------------------------------------------------------------------
__global__ void sent_kernel(const float* __restrict__ qemb,
                            const int*   __restrict__ slab,
                            float* loss_ptr) {
    const int bq  = blockIdx.x;
    const int b   = bq / NQv;
    const int tid = threadIdx.x;
    const int wid = tid >> 5, lane = tid & 31;

    const float* qrow = qemb + (size_t)bq * LL * FF;
    float d2[NN];
    #pragma unroll
    for (int n = 0; n < NN; n++) d2[n] = 0.f;
    for (int f = tid; f < FF; f += 256) {
        float qv = qrow[f];
        #pragma unroll
        for (int n = 0; n < NN; n++) {
            float d = g_sentproto[(b*NN + n)*FF + f] - qv;
            d2[n] += d * d;
        }
    }
    #pragma unroll
    for (int off = 16; off > 0; off >>= 1)
        #pragma unroll
        for (int n = 0; n < NN; n++)
            d2[n] += __shfl_xor_sync(0xffffffffu, d2[n], off);
    __shared__ float s_red[8][NN];
    if (lane == 0)
        #pragma unroll
        for (int n = 0; n < NN; n++) s_red[wid][n] = d2[n];
    __syncthreads();
    if (tid == 0) {
        float lg[NN];
        #pragma unroll
        for (int n = 0; n < NN; n++) {
            float s = 0.f;
            #pragma unroll
            for (int w = 0; w < 8; w++) s += s_red[w][n];
            lg[n] = -s;
        }
        float mx = lg[0]; int am = 0;
        #pragma unroll
        for (int n = 1; n < NN; n++) if (lg[n] > mx) { mx = lg[n]; am = n; }
        float se = 0.f;
        #pragma unroll
        for (int n = 0; n < NN; n++) se += expf(lg[n] - mx);
        int lab = slab[bq];
        float logp = lg[lab] - mx - logf(se);
        atomicAdd(loss_ptr, -logp / (float)BQ);
        g_sentpred[bq] = am;
    }
}

// ---------------------------------------------------------------------------
// token compute. grid=(BQ, LSEG), 256 threads. Each block: 16 l-rows.
// ---------------------------------------------------------------------------
__global__ void __launch_bounds__(256)
token_compute_kernel(const float* __restrict__ qemb,
                     const int*   __restrict__ qem,
                     const int*   __restrict__ qatt,
                     const int*   __restrict__ slab) {
    const int bq   = blockIdx.x;
    const int s    = blockIdx.y;
    const int b    = bq / NQv;
    const int tid  = threadIdx.x;
    const int wid  = tid >> 5, lane = tid & 31;
    const int FV   = FF / 4;   // 192

    __shared__ float4 s_proto[4 * (FF/4)];
    __shared__ float  s_p2[4];
    __shared__ float  s_ml[LPB * 4];
    __shared__ float  s_wb[8];

    const int cond = slab[bq];
    const float4* gp = (const float4*)(g_proto + (size_t)((b*NN + cond) * 4) * FF);
    for (int i = tid; i < 4 * FV; i += 256) s_proto[i] = __ldg(gp + i);
    __syncthreads();

    if (wid < 4) {
        float p = 0.f;
        #pragma unroll
        for (int j = 0; j < FV/32; j++) {
            float4 v = s_proto[wid*FV + lane + 32*j];
            p += v.x*v.x + v.y*v.y + v.z*v.z + v.w*v.w;
        }
        #pragma unroll
        for (int off = 16; off > 0; off >>= 1) p += __shfl_xor_sync(0xffffffffu, p, off);
        if (lane == 0) s_p2[wid] = p;
    }
    __syncthreads();

    const float4* qbase = (const float4*)(qemb + (size_t)bq * LL * FF);
    const int mlbase = bq * LL;
    float bce_acc = 0.f;

    #pragma unroll
    for (int r = 0; r < 2; r++) {
        const int ll = r * 8 + wid;       // 0..15 local
        const int l  = s * LPB + ll;      // global l
        const float4* qr = qbase + l * FV;
        float q2 = 0.f, c0 = 0.f, c1 = 0.f, c2 = 0.f, c3 = 0.f;
        #pragma unroll
        for (int j = 0; j < FV/32; j++) {
            int o = lane + 32*j;
            float4 v  = __ldg(qr + o);
            float4 w0 = s_proto[0*FV + o];
            float4 w1 = s_proto[1*FV + o];
            float4 w2 = s_proto[2*FV + o];
            float4 w3 = s_proto[3*FV + o];
            q2 += v.x*v.x + v.y*v.y + v.z*v.z + v.w*v.w;
            c0 += v.x*w0.x + v.y*w0.y + v.z*w0.z + v.w*w0.w;
            c1 += v.x*w1.x + v.y*w1.y + v.z*w1.z + v.w*w1.w;
            c2 += v.x*w2.x + v.y*w2.y + v.z*w2.z + v.w*w2.w;
            c3 += v.x*w3.x + v.y*w3.y + v.z*w3.z + v.w*w3.w;
        }
        #pragma unroll
        for (int off = 16; off > 0; off >>= 1) {
            q2 += __shfl_xor_sync(0xffffffffu, q2, off);
            c0 += __shfl_xor_sync(0xffffffffu, c0, off);
            c1 += __shfl_xor_sync(0xffffffffu, c1, off);
            c2 += __shfl_xor_sync(0xffffffffu, c2, off);
            c3 += __shfl_xor_sync(0xffffffffu, c3, off);
        }
        float att = (float)qatt[mlbase + l];
        int   em  = qem[mlbase + l];
        float tl[4];
        tl[0] = -(q2 + s_p2[0] - 2.f*c0);
        tl[1] = -(q2 + s_p2[1] - 2.f*c1);
        tl[2] = -(q2 + s_p2[2] - 2.f*c2);
        tl[3] = -(q2 + s_p2[3] - 2.f*c3);
        float bl = 0.f;
        #pragma unroll
        for (int c = 0; c < 4; c++) {
            float x = tl[c];
            float t = (em == c + 1) ? 1.f : 0.f;
            bl += fmaxf(x, 0.f) - x * t + log1pf(expf(-fabsf(x)));
        }
        bce_acc += bl * att;
        if (lane < 4) s_ml[ll*4 + lane] = tl[lane] - 1000.f * (1.f - att);
    }

    if (lane == 0) s_wb[wid] = bce_acc;
    __syncthreads();

    if (tid == 0) {
        float bs = 0.f;
        #pragma unroll
        for (int w = 0; w < 8; w++) bs += s_wb[w];
        atomicAdd(&g_bce[bq], bs);
    }
    if (tid < 4) {   // per-class first-occurrence argmax over this block's 16 rows
        float best = s_ml[0*4 + tid]; int bi = 0;
        #pragma unroll
        for (int ll = 1; ll < LPB; ll++) {
            float v = s_ml[ll*4 + tid];
            if (v > best) { best = v; bi = ll; }
        }
        g_segv[(bq*LSEG + s)*4 + tid] = best;
        g_segi[(bq*LSEG + s)*4 + tid] = s * LPB + bi;
    }
}

// ---------------------------------------------------------------------------
// token finalize: merge segments, loss term, write prediction. grid=BQ, 128thr.
// ---------------------------------------------------------------------------
__global__ void token_finalize_kernel(const int* __restrict__ qatt,
                                      float* loss_ptr,
                                      float* pred_out) {
    const int bq  = blockIdx.x;
    const int tid = threadIdx.x;
    __shared__ int   s_idx[4];
    __shared__ float s_att[4];

    if (tid < 4) {   // segments in order; strict > keeps first occurrence
        float best = g_segv[(bq*LSEG + 0)*4 + tid];
        int   bi   = g_segi[(bq*LSEG + 0)*4 + tid];
        #pragma unroll
        for (int s = 1; s < LSEG; s++) {
            float v = g_segv[(bq*LSEG + s)*4 + tid];
            if (v > best) { best = v; bi = g_segi[(bq*LSEG + s)*4 + tid]; }
        }
        s_idx[tid] = bi;
    }
    float a = (float)qatt[bq*LL + tid];
    #pragma unroll
    for (int off = 16; off > 0; off >>= 1) a += __shfl_xor_sync(0xffffffffu, a, off);
    if ((tid & 31) == 0) s_att[tid >> 5] = a;
    __syncthreads();

    if (tid == 0) {
        float as = s_att[0] + s_att[1] + s_att[2] + s_att[3];
        float per = g_bce[bq] / (as * 4.f + EPSF);
        atomicAdd(loss_ptr, per / (float)BQ);
    }
    {
        int pos = tid;
        int i0 = s_idx[0], i1 = s_idx[1], i2 = s_idx[2], i3 = s_idx[3];
        int pred = 0;
        if (pos == i0)             pred = 1;
        if (pos > i0 && pos <= i1) pred = 2;
        if (pos == i2)             pred = 3;
        if (pos > i2 && pos <= i3) pred = 4;
        int sp = g_sentpred[bq];
        pred_out[bq*LL + tid] = (float)((pred != 0) ? (4*sp + pred) : 0);
    }
}

// ---------------------------------------------------------------------------
extern "C" void kernel_launch(void* const* d_in, const int* in_sizes, int n_in,
                              void* d_out, int out_size) {
    const float* sup  = (const float*)d_in[0];
    const float* qemb = (const float*)d_in[1];
    const int*   sem  = (const int*)d_in[2];
    const int*   qem  = (const int*)d_in[3];
    const int*   sam  = (const int*)d_in[4];
    const int*   qatt = (const int*)d_in[5];
    const int*   slab = (const int*)d_in[6];

    float* out = (float*)d_out;
    float* scratch = nullptr;
    cudaGetSymbolAddress((void**)&scratch, g_scratch);

    float* loss_ptr;
    float* pred_ptr;
    if (out_size >= PRED_ELEMS + 1) {
        loss_ptr = out;
        pred_ptr = out + 1;
    } else if (out_size == PRED_ELEMS) {
        loss_ptr = scratch + PRED_ELEMS;
        pred_ptr = out;
    } else {
        loss_ptr = out;
        pred_ptr = scratch;
    }

    init_den_kernel<<<BB*NN + 1, 256>>>(sem, sam, loss_ptr);
    proto_partial_kernel<<<dim3(BB*NN, FF/128, ZSPLIT), 512>>>(sup, sem, sam);
    proto_norm_kernel<<<dim3(BB*NN, FF/128), 128>>>(sup);
    sent_kernel<<<BQ, 256>>>(qemb, slab, loss_ptr);
    token_compute_kernel<<<dim3(BQ, LSEG), 256>>>(qemb, qem, qatt, slab);
    token_finalize_kernel<<<BQ, 128>>>(qatt, loss_ptr, pred_ptr);
}

// round 5
// speedup vs baseline: 2.0624x; 1.1257x over previous
#include <cuda_runtime.h>
#include <math.h>

#define BB 4
#define NN 5
#define KK 5
#define QQ 5
#define LL 128
#define FF 768
#define NQv (NN*QQ)              // 25
#define BQ  (BB*NQv)             // 100
#define EPSF 1e-8f
#define PRED_ELEMS (BB*NQv*LL)   // 12800
#define ZSPLIT 4
#define ROWS_PER_Z (KK*LL/ZSPLIT)   // 160
#define LSEG 8
#define LPB (LL/LSEG)               // 16 l-rows per token block

// Scratch (no cudaMalloc allowed)
__device__ __align__(16) float g_proto[BB*NN*4*FF];             // class prototypes
__device__ __align__(16) float g_partial[ZSPLIT*BB*NN*4*FF];    // z-partial sums
__device__ __align__(16) float g_sentproto[BB*NN*FF];
__device__ int   g_denp[ZSPLIT*BB*NN*4];                        // per-z denominators
__device__ int   g_sentpred[BQ];
__device__ float g_bce[BQ];
__device__ float g_segv[BQ*LSEG*4];
__device__ int   g_segi[BQ*LSEG*4];
__device__ float g_scratch[PRED_ELEMS + 4];

// ---------------------------------------------------------------------------
// Kernel 1: proto partial sums + per-z denominators + loss/bce zeroing.
// grid=(B*N, F/128, ZSPLIT), block=512.
// ---------------------------------------------------------------------------
__global__ void proto_partial_kernel(const float* __restrict__ sup,
                                     const int*   __restrict__ sem,
                                     const int*   __restrict__ sam,
                                     float* loss_ptr) {
    const int bn    = blockIdx.x;
    const int fbase = blockIdx.y * 128;
    const int z     = blockIdx.z;
    const int tid   = threadIdx.x;
    const int fl    = tid & 127;
    const int grp   = tid >> 7;
    const int f     = fbase + fl;
    const int r0    = z * ROWS_PER_Z;

    __shared__ signed char s_cls[ROWS_PER_Z];
    __shared__ float s_part[4][4][128];
    __shared__ int   s_den[4];

    // fold init work into one block
    if (bn == 0 && blockIdx.y == 0 && z == 0) {
        if (tid == 0) *loss_ptr = 0.f;
        if (tid < BQ) g_bce[tid] = 0.f;
    }
    if (tid < 4) s_den[tid] = 0;
    __syncthreads();

    const int mbase = bn * KK * LL + r0;
    for (int i = tid; i < ROWS_PER_Z; i += 512) {
        int lab = sem[mbase + i];
        int att = sam[mbase + i];
        int c = (lab >= 1 && lab <= 4 && att > 0) ? (lab - 1) : -1;
        s_cls[i] = (signed char)c;
        if (blockIdx.y == 0 && c >= 0) atomicAdd(&s_den[c], 1);
    }
    __syncthreads();

    if (blockIdx.y == 0 && tid < 4)
        g_denp[(z*BB*NN + bn)*4 + tid] = s_den[tid];

    const float* p = sup + (size_t)(bn * KK * LL + r0) * FF + f;
    float a0 = 0.f, a1 = 0.f, a2 = 0.f, a3 = 0.f;
    #pragma unroll 4
    for (int i = grp; i < ROWS_PER_Z; i += 4) {
        int c = s_cls[i];
        if (c < 0) continue;
        float v = __ldg(p + (size_t)i * FF);
        if      (c == 0) a0 += v;
        else if (c == 1) a1 += v;
        else if (c == 2) a2 += v;
        else             a3 += v;
    }
    s_part[grp][0][fl] = a0;
    s_part[grp][1][fl] = a1;
    s_part[grp][2][fl] = a2;
    s_part[grp][3][fl] = a3;
    __syncthreads();

    if (tid < 128) {
        int obase = ((z*BB*NN + bn) * 4) * FF + fbase + tid;
        #pragma unroll
        for (int c = 0; c < 4; c++) {
            g_partial[obase + c*FF] =
                s_part[0][c][tid] + s_part[1][c][tid] +
                s_part[2][c][tid] + s_part[3][c][tid];
        }
    }
}

// ---------------------------------------------------------------------------
// Kernel 2: normalize partials -> g_proto; sentence prototypes. grid=(20,6),128
// ---------------------------------------------------------------------------
__global__ void proto_norm_kernel(const float* __restrict__ sup) {
    const int bn    = blockIdx.x;
    const int fbase = blockIdx.y * 128;
    const int tid   = threadIdx.x;
    const int f     = fbase + tid;

    #pragma unroll
    for (int c = 0; c < 4; c++) {
        int den = 0;
        #pragma unroll
        for (int z = 0; z < ZSPLIT; z++) den += g_denp[(z*BB*NN + bn)*4 + c];
        int idx = ((bn * 4) + c) * FF + f;
        float s = 0.f;
        #pragma unroll
        for (int z = 0; z < ZSPLIT; z++)
            s += g_partial[(z*BB*NN*4)*FF + idx];
        g_proto[idx] = s / ((float)den + EPSF);
    }
    float sp = 0.f;
    const float* ps = sup + (size_t)bn * (KK*LL*FF) + f;
    #pragma unroll
    for (int k = 0; k < KK; k++) sp += __ldg(ps + (size_t)k * LL * FF);
    g_sentproto[bn*FF + f] = sp * (1.0f / (float)KK);
}

// ---------------------------------------------------------------------------
// Kernel 3: token compute (+ fused sentence path in s==0 blocks).
// grid=(BQ, LSEG), 256 threads. Each block: 16 l-rows.
// ---------------------------------------------------------------------------
__global__ void __launch_bounds__(256)
token_compute_kernel(const float* __restrict__ qemb,
                     const int*   __restrict__ qem,
                     const int*   __restrict__ qatt,
                     const int*   __restrict__ slab,
                     float* loss_ptr) {
    const int bq   = blockIdx.x;
    const int s    = blockIdx.y;
    const int b    = bq / NQv;
    const int tid  = threadIdx.x;
    const int wid  = tid >> 5, lane = tid & 31;
    const int FV   = FF / 4;   // 192

    __shared__ float4 s_proto[4 * (FF/4)];
    __shared__ float  s_p2[4];
    __shared__ float  s_ml[LPB * 4];
    __shared__ float  s_wb[8];
    __shared__ float  s_red[8][NN];

    const int cond = slab[bq];
    const float4* gp = (const float4*)(g_proto + (size_t)((b*NN + cond) * 4) * FF);
    for (int i = tid; i < 4 * FV; i += 256) s_proto[i] = __ldg(gp + i);
    __syncthreads();

    if (wid < 4) {
        float p = 0.f;
        #pragma unroll
        for (int j = 0; j < FV/32; j++) {
            float4 v = s_proto[wid*FV + lane + 32*j];
            p += v.x*v.x + v.y*v.y + v.z*v.z + v.w*v.w;
        }
        #pragma unroll
        for (int off = 16; off > 0; off >>= 1) p += __shfl_xor_sync(0xffffffffu, p, off);
        if (lane == 0) s_p2[wid] = p;
    }
    __syncthreads();

    const float4* qbase = (const float4*)(qemb + (size_t)bq * LL * FF);
    const int mlbase = bq * LL;
    float bce_acc = 0.f;

    #pragma unroll
    for (int r = 0; r < 2; r++) {
        const int ll = r * 8 + wid;       // 0..15 local
        const int l  = s * LPB + ll;      // global l
        const float4* qr = qbase + l * FV;
        float q2 = 0.f, c0 = 0.f, c1 = 0.f, c2 = 0.f, c3 = 0.f;
        #pragma unroll
        for (int j = 0; j < FV/32; j++) {
            int o = lane + 32*j;
            float4 v  = __ldg(qr + o);
            float4 w0 = s_proto[0*FV + o];
            float4 w1 = s_proto[1*FV + o];
            float4 w2 = s_proto[2*FV + o];
            float4 w3 = s_proto[3*FV + o];
            q2 += v.x*v.x + v.y*v.y + v.z*v.z + v.w*v.w;
            c0 += v.x*w0.x + v.y*w0.y + v.z*w0.z + v.w*w0.w;
            c1 += v.x*w1.x + v.y*w1.y + v.z*w1.z + v.w*w1.w;
            c2 += v.x*w2.x + v.y*w2.y + v.z*w2.z + v.w*w2.w;
            c3 += v.x*w3.x + v.y*w3.y + v.z*w3.z + v.w*w3.w;
        }
        #pragma unroll
        for (int off = 16; off > 0; off >>= 1) {
            q2 += __shfl_xor_sync(0xffffffffu, q2, off);
            c0 += __shfl_xor_sync(0xffffffffu, c0, off);
            c1 += __shfl_xor_sync(0xffffffffu, c1, off);
            c2 += __shfl_xor_sync(0xffffffffu, c2, off);
            c3 += __shfl_xor_sync(0xffffffffu, c3, off);
        }
        float att = (float)qatt[mlbase + l];
        int   em  = qem[mlbase + l];
        float tl[4];
        tl[0] = -(q2 + s_p2[0] - 2.f*c0);
        tl[1] = -(q2 + s_p2[1] - 2.f*c1);
        tl[2] = -(q2 + s_p2[2] - 2.f*c2);
        tl[3] = -(q2 + s_p2[3] - 2.f*c3);
        float bl = 0.f;
        #pragma unroll
        for (int c = 0; c < 4; c++) {
            float x = tl[c];
            float t = (em == c + 1) ? 1.f : 0.f;
            bl += fmaxf(x, 0.f) - x * t + log1pf(expf(-fabsf(x)));
        }
        bce_acc += bl * att;
        if (lane < 4) s_ml[ll*4 + lane] = tl[lane] - 1000.f * (1.f - att);
    }

    if (lane == 0) s_wb[wid] = bce_acc;
    __syncthreads();

    if (tid == 0) {
        float bs = 0.f;
        #pragma unroll
        for (int w = 0; w < 8; w++) bs += s_wb[w];
        atomicAdd(&g_bce[bq], bs);
    }
    if (tid < 4) {   // per-class first-occurrence argmax over this block's 16 rows
        float best = s_ml[0*4 + tid]; int bi = 0;
        #pragma unroll
        for (int ll = 1; ll < LPB; ll++) {
            float v = s_ml[ll*4 + tid];
            if (v > best) { best = v; bi = ll; }
        }
        g_segv[(bq*LSEG + s)*4 + tid] = best;
        g_segi[(bq*LSEG + s)*4 + tid] = s * LPB + bi;
    }

    // -------- fused sentence path (one block per bq) --------
    if (s == 0) {
        const float* qrow = qemb + (size_t)bq * LL * FF;  // l=0 row (L1-warm)
        float d2[NN];
        #pragma unroll
        for (int n = 0; n < NN; n++) d2[n] = 0.f;
        for (int f = tid; f < FF; f += 256) {
            float qv = __ldg(qrow + f);
            #pragma unroll
            for (int n = 0; n < NN; n++) {
                float d = g_sentproto[(b*NN + n)*FF + f] - qv;
                d2[n] += d * d;
            }
        }
        #pragma unroll
        for (int off = 16; off > 0; off >>= 1)
            #pragma unroll
            for (int n = 0; n < NN; n++)
                d2[n] += __shfl_xor_sync(0xffffffffu, d2[n], off);
        if (lane == 0)
            #pragma unroll
            for (int n = 0; n < NN; n++) s_red[wid][n] = d2[n];
        __syncthreads();
        if (tid == 0) {
            float lg[NN];
            #pragma unroll
            for (int n = 0; n < NN; n++) {
                float sm = 0.f;
                #pragma unroll
                for (int w = 0; w < 8; w++) sm += s_red[w][n];
                lg[n] = -sm;
            }
            float mx = lg[0]; int am = 0;
            #pragma unroll
            for (int n = 1; n < NN; n++) if (lg[n] > mx) { mx = lg[n]; am = n; }
            float se = 0.f;
            #pragma unroll
            for (int n = 0; n < NN; n++) se += expf(lg[n] - mx);
            float logp = lg[cond] - mx - logf(se);
            atomicAdd(loss_ptr, -logp / (float)BQ);
            g_sentpred[bq] = am;
        }
    }
}

// ---------------------------------------------------------------------------
// Kernel 4: token finalize: merge segments, loss term, prediction. grid=BQ,128.
// ---------------------------------------------------------------------------
__global__ void token_finalize_kernel(const int* __restrict__ qatt,
                                      float* loss_ptr,
                                      float* pred_out) {
    const int bq  = blockIdx.x;
    const int tid = threadIdx.x;
    __shared__ int   s_idx[4];
    __shared__ float s_att[4];

    if (tid < 4) {   // segments in order; strict > keeps first occurrence
        float best = g_segv[(bq*LSEG + 0)*4 + tid];
        int   bi   = g_segi[(bq*LSEG + 0)*4 + tid];
        #pragma unroll
        for (int s = 1; s < LSEG; s++) {
            float v = g_segv[(bq*LSEG + s)*4 + tid];
            if (v > best) { best = v; bi = g_segi[(bq*LSEG + s)*4 + tid]; }
        }
        s_idx[tid] = bi;
    }
    float a = (float)qatt[bq*LL + tid];
    #pragma unroll
    for (int off = 16; off > 0; off >>= 1) a += __shfl_xor_sync(0xffffffffu, a, off);
    if ((tid & 31) == 0) s_att[tid >> 5] = a;
    __syncthreads();

    if (tid == 0) {
        float as = s_att[0] + s_att[1] + s_att[2] + s_att[3];
        float per = g_bce[bq] / (as * 4.f + EPSF);
        atomicAdd(loss_ptr, per / (float)BQ);
    }
    {
        int pos = tid;
        int i0 = s_idx[0], i1 = s_idx[1], i2 = s_idx[2], i3 = s_idx[3];
        int pred = 0;
        if (pos == i0)             pred = 1;
        if (pos > i0 && pos <= i1) pred = 2;
        if (pos == i2)             pred = 3;
        if (pos > i2 && pos <= i3) pred = 4;
        int sp = g_sentpred[bq];
        pred_out[bq*LL + tid] = (float)((pred != 0) ? (4*sp + pred) : 0);
    }
}

// ---------------------------------------------------------------------------
extern "C" void kernel_launch(void* const* d_in, const int* in_sizes, int n_in,
                              void* d_out, int out_size) {
    const float* sup  = (const float*)d_in[0];
    const float* qemb = (const float*)d_in[1];
    const int*   sem  = (const int*)d_in[2];
    const int*   qem  = (const int*)d_in[3];
    const int*   sam  = (const int*)d_in[4];
    const int*   qatt = (const int*)d_in[5];
    const int*   slab = (const int*)d_in[6];

    float* out = (float*)d_out;
    float* scratch = nullptr;
    cudaGetSymbolAddress((void**)&scratch, g_scratch);

    float* loss_ptr;
    float* pred_ptr;
    if (out_size >= PRED_ELEMS + 1) {
        loss_ptr = out;
        pred_ptr = out + 1;
    } else if (out_size == PRED_ELEMS) {
        loss_ptr = scratch + PRED_ELEMS;
        pred_ptr = out;
    } else {
        loss_ptr = out;
        pred_ptr = scratch;
    }

    proto_partial_kernel<<<dim3(BB*NN, FF/128, ZSPLIT), 512>>>(sup, sem, sam, loss_ptr);
    proto_norm_kernel<<<dim3(BB*NN, FF/128), 128>>>(sup);
    token_compute_kernel<<<dim3(BQ, LSEG), 256>>>(qemb, qem, qatt, slab, loss_ptr);
    token_finalize_kernel<<<BQ, 128>>>(qatt, loss_ptr, pred_ptr);
}